// round 9
// baseline (speedup 1.0000x reference)
#include <cuda_runtime.h>
#include <cstdint>
#include <math.h>

#define EMBED 1024
#define NHEADS 16
#define HD 64
#define BB 2
#define SS 2048
#define BHD (BB*NHEADS)   // 32
#define MROWS (BB*SS)     // 4096
#define SCALE 0.03125f    // 1/sqrt(1024)

// Pre-rounded (tf32) copies of inputs
__device__ float g_Xr[3][(size_t)MROWS*EMBED];
__device__ float g_Wr[3][(size_t)EMBED*EMBED];
// Projected Q,K in [B,H,S,D]; V stored TRANSPOSED as [B,H,D,S]. All tf32-rounded.
__device__ float g_Q[(size_t)BB*NHEADS*SS*HD];
__device__ float g_K[(size_t)BB*NHEADS*SS*HD];
__device__ float g_V[(size_t)BB*NHEADS*SS*HD];

__device__ __forceinline__ float to_tf32(float x) {
    float r;
    asm("cvt.rna.tf32.f32 %0, %1;" : "=f"(r) : "f"(x));
    return r;
}

__device__ __forceinline__ uint32_t smem_u32(const void* p) {
    uint32_t a;
    asm("{ .reg .u64 t; cvta.to.shared.u64 t, %1; cvt.u32.u64 %0, t; }" : "=r"(a) : "l"(p));
    return a;
}

// D = A(16x8 tf32) * B(8x8 tf32) + D, f32 accum. row.col layout.
__device__ __forceinline__ void mma8(float* d, const uint32_t* a, const uint32_t* b) {
    asm volatile(
        "mma.sync.aligned.m16n8k8.row.col.f32.tf32.tf32.f32 "
        "{%0,%1,%2,%3}, {%4,%5,%6,%7}, {%8,%9}, {%0,%1,%2,%3};"
        : "+f"(d[0]), "+f"(d[1]), "+f"(d[2]), "+f"(d[3])
        : "r"(a[0]), "r"(a[1]), "r"(a[2]), "r"(a[3]), "r"(b[0]), "r"(b[1]));
}

// ldmatrix x4 (b16 view of tf32 data)
__device__ __forceinline__ void ldsm_x4(uint32_t* r, uint32_t addr) {
    asm volatile("ldmatrix.sync.aligned.m8n8.x4.shared.b16 {%0,%1,%2,%3}, [%4];"
        : "=r"(r[0]), "=r"(r[1]), "=r"(r[2]), "=r"(r[3]) : "r"(addr));
}

// cp.async helpers
__device__ __forceinline__ void cp16(uint32_t dst, const void* src) {
    asm volatile("cp.async.cg.shared.global [%0], [%1], 16;" :: "r"(dst), "l"(src));
}
__device__ __forceinline__ void cp4(uint32_t dst, const void* src) {
    asm volatile("cp.async.ca.shared.global [%0], [%1], 4;" :: "r"(dst), "l"(src));
}
#define CP_COMMIT() asm volatile("cp.async.commit_group;" ::: "memory")
#define CP_WAIT0()  asm volatile("cp.async.wait_group 0;" ::: "memory")

// ---------------------------------------------------------------------------
// Kernel 0: elementwise tf32 rounding (x, W copies)
// ---------------------------------------------------------------------------
__global__ void __launch_bounds__(256) round4_kernel(const float* __restrict__ src,
                                                     float* __restrict__ dst, int n4)
{
    int i = blockIdx.x * 256 + threadIdx.x;
    if (i < n4) {
        float4 v = ((const float4*)src)[i];
        v.x = to_tf32(v.x); v.y = to_tf32(v.y);
        v.z = to_tf32(v.z); v.w = to_tf32(v.w);
        ((float4*)dst)[i] = v;
    }
}

// ---------------------------------------------------------------------------
// Kernel 1: QKV projection  y = tf32_round(x @ W^T + b)
// Q,K -> [B,H,S,D];  V -> [B,H,D,S] (transposed).
// BM=BN=128, BK=32. 8 warps as 2x4, warp tile 64x32.
// cp.async double-buffered staging of pre-rounded inputs, 1 barrier/chunk.
// ---------------------------------------------------------------------------
#define PSTR 36            // smem row stride (floats): 144B, %128=16 -> ldsm conflict-free
#define PBUF (2*128*PSTR)  // floats per buffer (A+B)
#define PROJ_SMEM_BYTES (2 * PBUF * 4)   // 73728

__global__ void __launch_bounds__(256, 2) proj_kernel(
    const float* __restrict__ bq, const float* __restrict__ bk, const float* __restrict__ bv)
{
    extern __shared__ float psm[];
    const uint32_t base = smem_u32(psm);

    const int z = blockIdx.z;
    const float* x = g_Xr[z];
    const float* W = g_Wr[z];
    const float* bias = (z == 0) ? bq : (z == 1) ? bk : bv;
    float* outp = (z == 0) ? g_Q : (z == 1) ? g_K : g_V;

    const int m0 = blockIdx.y * 128;
    const int n0 = blockIdx.x * 128;
    const int tid  = threadIdx.x;
    const int wid  = tid >> 5;
    const int lane = tid & 31;
    const int g    = lane >> 2;
    const int t4   = lane & 3;
    const int wm   = (wid >> 2) * 64;   // 0 or 64
    const int wn   = (wid & 3) * 32;    // 0,32,64,96

    const uint32_t a_l15 = (uint32_t)(lane & 15);
    const uint32_t a_hi4 = (uint32_t)((lane >> 4) << 2);
    const uint32_t b_row = (uint32_t)(((lane >> 4) << 3) + (lane & 7));
    const uint32_t b_c4  = (uint32_t)(((lane >> 3) & 1) << 2);

#define PROJ_ISSUE(C, BUF)                                                      \
    {                                                                           \
        const int k0_ = (C) * 32;                                               \
        const uint32_t ab_ = base + (uint32_t)((BUF) * PBUF) * 4u;              \
        const uint32_t bb_ = ab_ + 128u * PSTR * 4u;                            \
        _Pragma("unroll")                                                       \
        for (int i = 0; i < 4; i++) {                                           \
            int idx = tid + i * 256;                                            \
            int r = idx >> 3, c4 = idx & 7;                                     \
            cp16(ab_ + 4u * (uint32_t)(r * PSTR + c4 * 4),                      \
                 x + (size_t)(m0 + r) * EMBED + k0_ + c4 * 4);                  \
            cp16(bb_ + 4u * (uint32_t)(r * PSTR + c4 * 4),                      \
                 W + (size_t)(n0 + r) * EMBED + k0_ + c4 * 4);                  \
        }                                                                       \
        CP_COMMIT();                                                            \
    }

    float acc[4][4][4];
    #pragma unroll
    for (int mi = 0; mi < 4; mi++)
        #pragma unroll
        for (int nj = 0; nj < 4; nj++)
            #pragma unroll
            for (int e = 0; e < 4; e++) acc[mi][nj][e] = 0.f;

    PROJ_ISSUE(0, 0);

    for (int c = 0; c < EMBED / 32; c++) {
        const int buf = c & 1;
        CP_WAIT0();
        __syncthreads();
        if (c + 1 < EMBED / 32) PROJ_ISSUE(c + 1, buf ^ 1);

        const uint32_t asb = base + (uint32_t)(buf * PBUF) * 4u;
        const uint32_t bsb = asb + 128u * PSTR * 4u;
        #pragma unroll
        for (int ks = 0; ks < 4; ks++) {
            uint32_t af[4][4], bf4[2][4];
            #pragma unroll
            for (int mi = 0; mi < 4; mi++)
                ldsm_x4(af[mi], asb + 4u * ((uint32_t)(wm + mi * 16) * PSTR + a_l15 * PSTR
                                            + (uint32_t)(ks * 8) + a_hi4));
            #pragma unroll
            for (int p = 0; p < 2; p++)
                ldsm_x4(bf4[p], bsb + 4u * ((uint32_t)(wn + p * 16) * PSTR + b_row * PSTR
                                            + (uint32_t)(ks * 8) + b_c4));
            #pragma unroll
            for (int mi = 0; mi < 4; mi++)
                #pragma unroll
                for (int nj = 0; nj < 4; nj++)
                    mma8(acc[mi][nj], af[mi], &bf4[nj >> 1][(nj & 1) * 2]);
        }
    }

    // epilogue: +bias, tf32-round, scatter
    #pragma unroll
    for (int mi = 0; mi < 4; mi++) {
        int r0 = m0 + wm + mi * 16 + g;
        int r1 = r0 + 8;
        int bb0 = r0 >> 11, s0 = r0 & 2047;
        int bb1 = r1 >> 11, s1 = r1 & 2047;
        #pragma unroll
        for (int nj = 0; nj < 4; nj++) {
            int f = n0 + wn + nj * 8 + 2 * t4;
            int h = f >> 6, dd = f & 63;
            float b0 = bias[f], b1 = bias[f + 1];
            float v0 = to_tf32(acc[mi][nj][0] + b0);
            float v1 = to_tf32(acc[mi][nj][1] + b1);
            float v2 = to_tf32(acc[mi][nj][2] + b0);
            float v3 = to_tf32(acc[mi][nj][3] + b1);
            if (z == 2) {
                // V transposed: [B,H,D,S]
                float* base0 = outp + (((size_t)(bb0 * NHEADS + h)) * HD + dd) * SS;
                float* base1 = outp + (((size_t)(bb1 * NHEADS + h)) * HD + dd) * SS;
                base0[s0] = v0; base0[SS + s0] = v1;
                base1[s1] = v2; base1[SS + s1] = v3;
            } else {
                float* p0 = outp + (((size_t)(bb0 * NHEADS + h)) * SS + s0) * HD + dd;
                float* p1 = outp + (((size_t)(bb1 * NHEADS + h)) * SS + s1) * HD + dd;
                *(float2*)p0 = make_float2(v0, v1);
                *(float2*)p1 = make_float2(v2, v3);
            }
        }
    }
}

// ---------------------------------------------------------------------------
// Kernel 2: attention. 256 threads (8 warps), q-tile 128, warp tile 16x64.
// cp.async double-buffered K/V^T staging, 1 barrier/tile.
// P permuted acc->A-frag via shfl; V^T B-frags via ldmatrix; row sums in regs.
// ---------------------------------------------------------------------------
#define ASTR 68   // stride (272B, %128=16: ldsm conflict-free)

#define OFF_Q  0
#define OFF_K  (128 * ASTR)              // 8704
#define OFF_VT (OFF_K + 2 * 64 * ASTR)   // 17408
#define OFF_MK (OFF_VT + 2 * 64 * ASTR)  // 26112 (ints)
#define ASM_FLOATS (OFF_MK + 128)        // 26240 floats = 104960 B

__global__ void __launch_bounds__(256, 2) attn_kernel(const int* __restrict__ amask,
                                                      float* __restrict__ out)
{
    extern __shared__ float sm[];
    float* Qs = sm;
    const uint32_t qsb = smem_u32(sm);

    const int tid  = threadIdx.x;
    const int wid  = tid >> 5;
    const int lane = tid & 31;
    const int g    = lane >> 2;
    const int t4   = lane & 3;
    const int wm   = wid * 16;

    const uint32_t a_l15 = (uint32_t)(lane & 15);
    const uint32_t a_hi4 = (uint32_t)((lane >> 4) << 2);
    const uint32_t b_row = (uint32_t)(((lane >> 4) << 3) + (lane & 7));
    const uint32_t b_c4  = (uint32_t)(((lane >> 3) & 1) << 2);

    const int bh = blockIdx.x;
    const int b  = bh >> 4;
    const int q0 = blockIdx.y * 128;

    const float* Qb = g_Q + (size_t)bh * SS * HD;
    const float* Kb = g_K + (size_t)bh * SS * HD;
    const float* Vb = g_V + (size_t)bh * HD * SS;   // transposed [d][s]

    // ---- stage Q tile [128x64] (persistent; pre-rounded) ----
    #pragma unroll
    for (int i = 0; i < 8; i++) {
        int idx = tid + i * 256;
        int r = idx >> 4, c4 = idx & 15;
        *(float4*)&Qs[r * ASTR + c4 * 4] = *(const float4*)(Qb + (size_t)(q0 + r) * HD + c4 * 4);
    }

    // issue tile KT's K/V^T/mask copies into buffer BUF
#define ISSUE_TILE(KT, BUF)                                                     \
    {                                                                           \
        const int k0_ = (KT) * 64;                                              \
        const uint32_t kb_ = qsb + 4u * (uint32_t)(OFF_K  + (BUF) * 64 * ASTR); \
        const uint32_t vb_ = qsb + 4u * (uint32_t)(OFF_VT + (BUF) * 64 * ASTR); \
        _Pragma("unroll")                                                       \
        for (int i = 0; i < 4; i++) {                                           \
            int idx = tid + i * 256;                                            \
            int r = idx >> 4, c4 = idx & 15;                                    \
            cp16(kb_ + 4u * (uint32_t)(r * ASTR + c4 * 4),                      \
                 Kb + (size_t)(k0_ + r) * HD + c4 * 4);                         \
            cp16(vb_ + 4u * (uint32_t)(r * ASTR + c4 * 4),                      \
                 Vb + (size_t)r * SS + k0_ + c4 * 4);                           \
        }                                                                       \
        if (tid < 64)                                                           \
            cp4(qsb + 4u * (uint32_t)(OFF_MK + (BUF) * 64 + tid),               \
                amask + (size_t)b * SS + k0_ + tid);                            \
        CP_COMMIT();                                                            \
    }

    ISSUE_TILE(0, 0);
    __syncthreads();   // Qs visible

    float oacc[8][4];
    #pragma unroll
    for (int nj = 0; nj < 8; nj++)
        #pragma unroll
        for (int e = 0; e < 4; e++) oacc[nj][e] = 0.f;
    float lrA = 0.f, lrB = 0.f;

    const int srcA = (lane & 28) | (t4 >> 1);
    const int srcB = srcA + 2;
    const bool odd = (t4 & 1) != 0;

    const uint32_t qfb = qsb + 4u * ((uint32_t)wm * ASTR + a_l15 * ASTR + a_hi4);

    for (int kt = 0; kt < SS / 64; kt++) {
        const int buf = kt & 1;

        CP_WAIT0();        // my copies for tile kt done
        __syncthreads();   // all copies visible; all warps past compute(kt-1)

        if (kt + 1 < SS / 64) ISSUE_TILE(kt + 1, buf ^ 1);

        const uint32_t ksb = qsb + 4u * (uint32_t)(OFF_K  + buf * 64 * ASTR)
                           + 4u * (b_row * ASTR + b_c4);
        const uint32_t vsb = qsb + 4u * (uint32_t)(OFF_VT + buf * 64 * ASTR)
                           + 4u * (b_row * ASTR + b_c4);
        const int* mki = (const int*)(sm + OFF_MK) + buf * 64;

        // ---- MMA1: S[16x64] = Q K^T ----
        float sa[8][4];
        #pragma unroll
        for (int nj = 0; nj < 8; nj++)
            #pragma unroll
            for (int e = 0; e < 4; e++) sa[nj][e] = 0.f;

        #pragma unroll
        for (int ks = 0; ks < 8; ks++) {
            uint32_t qf[4];
            ldsm_x4(qf, qfb + 4u * (uint32_t)(ks * 8));
            uint32_t bq[4][4];
            #pragma unroll
            for (int p = 0; p < 4; p++)
                ldsm_x4(bq[p], ksb + 4u * (uint32_t)(p * 16 * ASTR + ks * 8));
            #pragma unroll
            for (int nj = 0; nj < 8; nj++)
                mma8(sa[nj], qf, &bq[nj >> 1][(nj & 1) * 2]);
        }

        // ---- softmax piece: p = mask ? exp(s/32) : 0; row sums in regs ----
        #pragma unroll
        for (int nj = 0; nj < 8; nj++) {
            bool m0 = mki[nj * 8 + 2 * t4] != 0;
            bool m1 = mki[nj * 8 + 2 * t4 + 1] != 0;
            float p0 = m0 ? __expf(sa[nj][0] * SCALE) : 0.f;
            float p1 = m1 ? __expf(sa[nj][1] * SCALE) : 0.f;
            float p2 = m0 ? __expf(sa[nj][2] * SCALE) : 0.f;
            float p3 = m1 ? __expf(sa[nj][3] * SCALE) : 0.f;
            sa[nj][0] = p0; sa[nj][1] = p1;
            sa[nj][2] = p2; sa[nj][3] = p3;
            lrA += p0 + p1;
            lrB += p2 + p3;
        }

        // ---- MMA2: O += P V  (A via shfl permute, B = V^T frags via ldmatrix) ----
        #pragma unroll
        for (int ks = 0; ks < 8; ks++) {
            uint32_t pa[4];
            {
                float v0 = __shfl_sync(0xFFFFFFFFu, sa[ks][0], srcA);
                float v1 = __shfl_sync(0xFFFFFFFFu, sa[ks][1], srcA);
                float v2 = __shfl_sync(0xFFFFFFFFu, sa[ks][2], srcA);
                float v3 = __shfl_sync(0xFFFFFFFFu, sa[ks][3], srcA);
                float w0 = __shfl_sync(0xFFFFFFFFu, sa[ks][0], srcB);
                float w1 = __shfl_sync(0xFFFFFFFFu, sa[ks][1], srcB);
                float w2 = __shfl_sync(0xFFFFFFFFu, sa[ks][2], srcB);
                float w3 = __shfl_sync(0xFFFFFFFFu, sa[ks][3], srcB);
                pa[0] = __float_as_uint(to_tf32(odd ? v1 : v0));
                pa[1] = __float_as_uint(to_tf32(odd ? v3 : v2));
                pa[2] = __float_as_uint(to_tf32(odd ? w1 : w0));
                pa[3] = __float_as_uint(to_tf32(odd ? w3 : w2));
            }
            uint32_t bv[4][4];
            #pragma unroll
            for (int p = 0; p < 4; p++)
                ldsm_x4(bv[p], vsb + 4u * (uint32_t)(p * 16 * ASTR + ks * 8));
            #pragma unroll
            for (int nj = 0; nj < 8; nj++)
                mma8(oacc[nj], pa, &bv[nj >> 1][(nj & 1) * 2]);
        }
    }

    // ---- reduce row sums across quad, normalize, store ----
    lrA += __shfl_xor_sync(0xFFFFFFFFu, lrA, 1);
    lrA += __shfl_xor_sync(0xFFFFFFFFu, lrA, 2);
    lrB += __shfl_xor_sync(0xFFFFFFFFu, lrB, 1);
    lrB += __shfl_xor_sync(0xFFFFFFFFu, lrB, 2);

    const int r0 = wm + g;
    const int r1 = r0 + 8;
    const float il0 = 1.f / lrA;
    const float il1 = 1.f / lrB;
    #pragma unroll
    for (int nj = 0; nj < 8; nj++) {
        int c0 = nj * 8 + 2 * t4;
        float* p0 = out + ((size_t)bh * SS + q0 + r0) * HD + c0;
        float* p1 = out + ((size_t)bh * SS + q0 + r1) * HD + c0;
        *(float2*)p0 = make_float2(oacc[nj][0] * il0, oacc[nj][1] * il0);
        *(float2*)p1 = make_float2(oacc[nj][2] * il1, oacc[nj][3] * il1);
    }
}

// ---------------------------------------------------------------------------
extern "C" void kernel_launch(void* const* d_in, const int* in_sizes, int n_in,
                              void* d_out, int out_size)
{
    (void)in_sizes; (void)n_in; (void)out_size;
    const float* q  = (const float*)d_in[0];
    const float* k  = (const float*)d_in[1];
    const float* v  = (const float*)d_in[2];
    const int*   am = (const int*)  d_in[3];
    const float* Wq = (const float*)d_in[4];
    const float* bq = (const float*)d_in[5];
    const float* Wk = (const float*)d_in[6];
    const float* bk = (const float*)d_in[7];
    const float* Wv = (const float*)d_in[8];
    const float* bv = (const float*)d_in[9];

    static int attr_set = 0;
    static float *xr0, *xr1, *xr2, *wr0, *wr1, *wr2;
    if (!attr_set) {
        cudaFuncSetAttribute(attn_kernel, cudaFuncAttributeMaxDynamicSharedMemorySize,
                             ASM_FLOATS * (int)sizeof(float));
        cudaFuncSetAttribute(proj_kernel, cudaFuncAttributeMaxDynamicSharedMemorySize,
                             PROJ_SMEM_BYTES);
        cudaGetSymbolAddress((void**)&xr0, g_Xr); xr1 = xr0 + (size_t)MROWS*EMBED;
        xr2 = xr1 + (size_t)MROWS*EMBED;
        cudaGetSymbolAddress((void**)&wr0, g_Wr); wr1 = wr0 + (size_t)EMBED*EMBED;
        wr2 = wr1 + (size_t)EMBED*EMBED;
        attr_set = 1;
    }

    const int nx4 = MROWS * EMBED / 4;     // 1,048,576
    const int nw4 = EMBED * EMBED / 4;     // 262,144
    round4_kernel<<<(nx4 + 255) / 256, 256>>>(q,  xr0, nx4);
    round4_kernel<<<(nx4 + 255) / 256, 256>>>(k,  xr1, nx4);
    round4_kernel<<<(nx4 + 255) / 256, 256>>>(v,  xr2, nx4);
    round4_kernel<<<(nw4 + 255) / 256, 256>>>(Wq, wr0, nw4);
    round4_kernel<<<(nw4 + 255) / 256, 256>>>(Wk, wr1, nw4);
    round4_kernel<<<(nw4 + 255) / 256, 256>>>(Wv, wr2, nw4);

    dim3 pgrid(EMBED / 128, MROWS / 128, 3);   // (8, 32, 3)
    proj_kernel<<<pgrid, 256, PROJ_SMEM_BYTES>>>(bq, bk, bv);

    dim3 agrid(BHD, SS / 128);                 // (32, 16)
    attn_kernel<<<agrid, 256, ASM_FLOATS * sizeof(float)>>>(am, (float*)d_out);
}